// round 14
// baseline (speedup 1.0000x reference)
#include <cuda_runtime.h>
#include <math_constants.h>

// Problem shape (fixed by the dataset)
#define BB 4
#define HH 32
#define DD 128
#define SS 8192
#define NSPLITS 16        // measured-optimal granularity; grid = 2048 CTAs
#define NWARPS 2          // 64-thread CTAs -> ~28 warps/SM, single wave
#define NBH (BB * HH)     // 128
#define SCALE 0.08838834764831845f   // 1/sqrt(128)

// Scratch for split-KV partials (device globals: allocation-free)
__device__ float g_pm[NBH * NSPLITS];
__device__ float g_pl[NBH * NSPLITS];
__device__ float g_pacc[NBH * NSPLITS * DD];
__device__ int   g_cnt[NBH];   // zero-init; self-resetting -> graph-replay safe

__device__ __forceinline__ float warp_sum(float v) {
#pragma unroll
    for (int o = 16; o > 0; o >>= 1)
        v += __shfl_xor_sync(0xffffffffu, v, o);
    return v;
}

__device__ __forceinline__ float dot4(const float4 a, const float4 b) {
    return a.x * b.x + a.y * b.y + a.z * b.z + a.w * b.w;
}

__device__ __forceinline__ float4 ldcs4(const float* p) {
    return __ldcs(reinterpret_cast<const float4*>(p));
}

// ---------------------------------------------------------------------------
// Champion shape (NSPLITS=16, 2-warp CTAs, fused combine) with a SOFTWARE-
// PIPELINED mainloop: double-buffered 2-position groups. The next group's 4
// loads are issued BEFORE the current group's shuffle/exp phase, so ~8 loads
// stay in flight continuously (same peak MLP as the bursty 4x-unroll champion,
// but a smooth issue pattern). Regs ~65-70: still >=14 CTAs/SM, occupancy kept.
// ---------------------------------------------------------------------------
__global__ __launch_bounds__(NWARPS * 32)
void attn_split_kernel(const float* __restrict__ x,
                       const float* __restrict__ kv,
                       const int*   __restrict__ cur_pos,
                       float*       __restrict__ out) {
    const int bid   = blockIdx.x;            // bh*NSPLITS + split
    const int bh    = bid / NSPLITS;
    const int h     = bh % HH;
    const int b     = bh / HH;
    const int split = bid % NSPLITS;

    const int tid  = threadIdx.x;
    const int lane = tid & 31;
    const int w    = tid >> 5;

    const int len   = *cur_pos + 1;                      // valid positions
    const int chunk = (len + NSPLITS - 1) / NSPLITS;
    const int s0    = split * chunk;
    const int s1    = min(len, s0 + chunk);

    // q[b,0,h,:] — lane's 4 dims
    const float4 q = *reinterpret_cast<const float4*>(
        x + (size_t)(b * HH + h) * DD + lane * 4);

    const size_t row_stride = (size_t)HH * DD;           // stride over s
    const size_t kv_half    = (size_t)BB * SS * HH * DD; // K->V offset
    const float* Kp = kv + (size_t)b * SS * row_stride + (size_t)h * DD + lane * 4;
    const float* Vp = Kp + kv_half;

    float  m = -CUDART_INF_F;
    float  l = 0.f;
    float4 acc = make_float4(0.f, 0.f, 0.f, 0.f);

    const int step  = NWARPS;        // position stride within warp
    const int gstep = 2 * NWARPS;    // group stride (2 positions per group)

    int s = s0 + w;

    // ---- software pipeline: double-buffered 2-position groups ----
    float4 kA, vA, kB, vB;
    bool have = (s + step) < s1;     // a full pair exists at s
    if (have) {
        kA = ldcs4(Kp + (size_t)(s       ) * row_stride);
        vA = ldcs4(Vp + (size_t)(s       ) * row_stride);
        kB = ldcs4(Kp + (size_t)(s + step) * row_stride);
        vB = ldcs4(Vp + (size_t)(s + step) * row_stride);
    }
    while (have) {
        const int sn = s + gstep;
        const bool haveN = (sn + step) < s1;
        float4 kAn, vAn, kBn, vBn;
        if (haveN) {                 // issue next group's loads FIRST
            kAn = ldcs4(Kp + (size_t)(sn       ) * row_stride);
            vAn = ldcs4(Vp + (size_t)(sn       ) * row_stride);
            kBn = ldcs4(Kp + (size_t)(sn + step) * row_stride);
            vBn = ldcs4(Vp + (size_t)(sn + step) * row_stride);
        }

        // process current group while next group's loads are in flight
        const float scA = warp_sum(dot4(kA, q)) * SCALE;
        const float scB = warp_sum(dot4(kB, q)) * SCALE;

        const float mn   = fmaxf(m, fmaxf(scA, scB));
        const float corr = __expf(m - mn);
        const float pA   = __expf(scA - mn);
        const float pB   = __expf(scB - mn);
        m = mn;
        l = l * corr + (pA + pB);
        acc.x = acc.x * corr + pA * vA.x + pB * vB.x;
        acc.y = acc.y * corr + pA * vA.y + pB * vB.y;
        acc.z = acc.z * corr + pA * vA.z + pB * vB.z;
        acc.w = acc.w * corr + pA * vA.w + pB * vB.w;

        kA = kAn; vA = vAn; kB = kBn; vB = vBn;
        s = sn; have = haveN;
    }
    // tail: remaining positions (at most 2 per warp)
    for (; s < s1; s += step) {
        const float4 kk = ldcs4(Kp + (size_t)s * row_stride);
        const float4 vv = ldcs4(Vp + (size_t)s * row_stride);
        const float sc = warp_sum(dot4(kk, q)) * SCALE;
        const float mn   = fmaxf(m, sc);
        const float corr = __expf(m - mn);
        const float p    = __expf(sc - mn);
        m = mn;
        l = l * corr + p;
        acc.x = acc.x * corr + p * vv.x;
        acc.y = acc.y * corr + p * vv.y;
        acc.z = acc.z * corr + p * vv.z;
        acc.w = acc.w * corr + p * vv.w;
    }

    // ---- combine the NWARPS warps of this CTA ----
    __shared__ float sm_m[NWARPS];
    __shared__ float sm_l[NWARPS];
    __shared__ float sm_acc[NWARPS][DD];

    if (lane == 0) { sm_m[w] = m; sm_l[w] = l; }
    sm_acc[w][lane * 4 + 0] = acc.x;
    sm_acc[w][lane * 4 + 1] = acc.y;
    sm_acc[w][lane * 4 + 2] = acc.z;
    sm_acc[w][lane * 4 + 3] = acc.w;
    __syncthreads();

    if (w == 0) {
        float M = -CUDART_INF_F;
#pragma unroll
        for (int i = 0; i < NWARPS; i++) M = fmaxf(M, sm_m[i]);

        float  L = 0.f;
        float4 o = make_float4(0.f, 0.f, 0.f, 0.f);
#pragma unroll
        for (int i = 0; i < NWARPS; i++) {
            if (sm_l[i] == 0.f) continue;   // warp saw no positions
            const float c = __expf(sm_m[i] - M);
            L += c * sm_l[i];
            o.x += c * sm_acc[i][lane * 4 + 0];
            o.y += c * sm_acc[i][lane * 4 + 1];
            o.z += c * sm_acc[i][lane * 4 + 2];
            o.w += c * sm_acc[i][lane * 4 + 3];
        }
        g_pm[bid] = M;
        g_pl[bid] = L;
        reinterpret_cast<float4*>(g_pacc + (size_t)bid * DD)[lane] = o;

        // ---- fused cross-split combine: last CTA per (b,h) merges ----
        __threadfence();
        int done = 0;
        if (lane == 0) done = atomicAdd(&g_cnt[bh], 1);
        done = __shfl_sync(0xffffffffu, done, 0);

        if (done == NSPLITS - 1) {
            float GM = -CUDART_INF_F;
#pragma unroll
            for (int i = 0; i < NSPLITS; i++)
                GM = fmaxf(GM, __ldcg(&g_pm[bh * NSPLITS + i]));

            float  GL = 0.f;
            float4 go = make_float4(0.f, 0.f, 0.f, 0.f);
#pragma unroll 4
            for (int i = 0; i < NSPLITS; i++) {
                const int idx = bh * NSPLITS + i;
                const float li = __ldcg(&g_pl[idx]);
                if (li == 0.f) continue;
                const float c = __expf(__ldcg(&g_pm[idx]) - GM);
                GL += c * li;
                const float4 a = __ldcg(reinterpret_cast<const float4*>(
                    g_pacc + (size_t)idx * DD) + lane);
                go.x += c * a.x; go.y += c * a.y;
                go.z += c * a.z; go.w += c * a.w;
            }
            const float inv = 1.f / GL;
            const float4 r = make_float4(go.x * inv, go.y * inv,
                                         go.z * inv, go.w * inv);
            reinterpret_cast<float4*>(out + (size_t)bh * DD)[lane] = r;

            if (lane == 0) g_cnt[bh] = 0;   // reset for next graph replay
        }
    }
}

// ---------------------------------------------------------------------------
extern "C" void kernel_launch(void* const* d_in, const int* in_sizes, int n_in,
                              void* d_out, int out_size) {
    // Identify inputs defensively by element count:
    //   x: B*H*D = 16384 fp32, kv: 2*B*S*H*D fp32 (largest), current_pos: 1 int
    const float* x  = nullptr;
    const float* kv = nullptr;
    const int*   cp = nullptr;
    long long best_kv = -1;
    for (int i = 0; i < n_in; i++) {
        if (in_sizes[i] == 1) cp = (const int*)d_in[i];
        else if (in_sizes[i] == BB * HH * DD) x = (const float*)d_in[i];
        else if ((long long)in_sizes[i] > best_kv) {
            best_kv = in_sizes[i];
            kv = (const float*)d_in[i];
        }
    }

    attn_split_kernel<<<NBH * NSPLITS, NWARPS * 32>>>(x, kv, cp, (float*)d_out);
}

// round 15
// speedup vs baseline: 1.0111x; 1.0111x over previous
#include <cuda_runtime.h>
#include <math_constants.h>

// Problem shape (fixed by the dataset)
#define BB 4
#define HH 32
#define DD 128
#define SS 8192
#define NSPLITS 16        // measured-optimal granularity; grid = 2048 CTAs
#define NWARPS 2          // 64-thread CTAs -> ~28 warps/SM, single wave
#define NBH (BB * HH)     // 128
#define SCALE 0.08838834764831845f   // 1/sqrt(128)

// Scratch for split-KV partials (device globals: allocation-free)
__device__ float g_pm[NBH * NSPLITS];
__device__ float g_pl[NBH * NSPLITS];
__device__ float g_pacc[NBH * NSPLITS * DD];
__device__ int   g_cnt[NBH];   // zero-init; self-resetting -> graph-replay safe

__device__ __forceinline__ float warp_sum(float v) {
#pragma unroll
    for (int o = 16; o > 0; o >>= 1)
        v += __shfl_xor_sync(0xffffffffu, v, o);
    return v;
}

__device__ __forceinline__ float dot4(const float4 a, const float4 b) {
    return a.x * b.x + a.y * b.y + a.z * b.z + a.w * b.w;
}

__device__ __forceinline__ float4 ldcs4(const float* p) {
    return __ldcs(reinterpret_cast<const float4*>(p));
}

// ---------------------------------------------------------------------------
// FINAL champion (best measured 82.4us @ ~79% DRAM of 8TB/s spec; ~81% of the
// 67us ideal-bandwidth floor).
// One CTA = one (b, h, split). Warps stride positions inside the split chunk.
// Lane owns dims [4*lane, 4*lane+4). 4x position unroll -> 8 streaming float4
// loads in flight per warp (interior optimum: MLP 4->86.1, 8->82.4, 16->96.3).
// Fused combine: last CTA per (b,h) merges split partials via atomic counter.
// Falsified alternatives: higher occupancy (R3), larger DRAM granule (R4/R8),
// single-warp CTAs (R9), work-stealing (R10), deeper unroll (R12),
// software-pipelined load issue (R14).
// ---------------------------------------------------------------------------
__global__ __launch_bounds__(NWARPS * 32)
void attn_split_kernel(const float* __restrict__ x,
                       const float* __restrict__ kv,
                       const int*   __restrict__ cur_pos,
                       float*       __restrict__ out) {
    const int bid   = blockIdx.x;            // bh*NSPLITS + split
    const int bh    = bid / NSPLITS;
    const int h     = bh % HH;
    const int b     = bh / HH;
    const int split = bid % NSPLITS;

    const int tid  = threadIdx.x;
    const int lane = tid & 31;
    const int w    = tid >> 5;

    const int len   = *cur_pos + 1;                      // valid positions
    const int chunk = (len + NSPLITS - 1) / NSPLITS;
    const int s0    = split * chunk;
    const int s1    = min(len, s0 + chunk);

    // q[b,0,h,:] — lane's 4 dims
    const float4 q = *reinterpret_cast<const float4*>(
        x + (size_t)(b * HH + h) * DD + lane * 4);

    const size_t row_stride = (size_t)HH * DD;           // stride over s
    const size_t kv_half    = (size_t)BB * SS * HH * DD; // K->V offset
    const float* Kp = kv + (size_t)b * SS * row_stride + (size_t)h * DD + lane * 4;
    const float* Vp = Kp + kv_half;

    float  m = -CUDART_INF_F;
    float  l = 0.f;
    float4 acc = make_float4(0.f, 0.f, 0.f, 0.f);

    int s = s0 + w;
    // 4x unroll: 8 streaming float4 loads in flight before dependent math,
    // single max/rescale per group -> 4 independent __expf's.
    for (; s + 3 * NWARPS < s1; s += 4 * NWARPS) {
        const float4 k0 = ldcs4(Kp + (size_t)(s             ) * row_stride);
        const float4 v0 = ldcs4(Vp + (size_t)(s             ) * row_stride);
        const float4 k1 = ldcs4(Kp + (size_t)(s +     NWARPS) * row_stride);
        const float4 v1 = ldcs4(Vp + (size_t)(s +     NWARPS) * row_stride);
        const float4 k2 = ldcs4(Kp + (size_t)(s + 2 * NWARPS) * row_stride);
        const float4 v2 = ldcs4(Vp + (size_t)(s + 2 * NWARPS) * row_stride);
        const float4 k3 = ldcs4(Kp + (size_t)(s + 3 * NWARPS) * row_stride);
        const float4 v3 = ldcs4(Vp + (size_t)(s + 3 * NWARPS) * row_stride);

        const float sc0 = warp_sum(dot4(k0, q)) * SCALE;
        const float sc1 = warp_sum(dot4(k1, q)) * SCALE;
        const float sc2 = warp_sum(dot4(k2, q)) * SCALE;
        const float sc3 = warp_sum(dot4(k3, q)) * SCALE;

        const float mn = fmaxf(fmaxf(fmaxf(m, sc0), fmaxf(sc1, sc2)), sc3);
        const float corr = __expf(m - mn);
        const float p0 = __expf(sc0 - mn);
        const float p1 = __expf(sc1 - mn);
        const float p2 = __expf(sc2 - mn);
        const float p3 = __expf(sc3 - mn);
        m = mn;
        l = l * corr + ((p0 + p1) + (p2 + p3));
        acc.x = acc.x * corr + (p0 * v0.x + p1 * v1.x) + (p2 * v2.x + p3 * v3.x);
        acc.y = acc.y * corr + (p0 * v0.y + p1 * v1.y) + (p2 * v2.y + p3 * v3.y);
        acc.z = acc.z * corr + (p0 * v0.z + p1 * v1.z) + (p2 * v2.z + p3 * v3.z);
        acc.w = acc.w * corr + (p0 * v0.w + p1 * v1.w) + (p2 * v2.w + p3 * v3.w);
    }
    for (; s < s1; s += NWARPS) {
        const float4 kk = ldcs4(Kp + (size_t)s * row_stride);
        const float4 vv = ldcs4(Vp + (size_t)s * row_stride);
        const float sc = warp_sum(dot4(kk, q)) * SCALE;
        const float mn   = fmaxf(m, sc);
        const float corr = __expf(m - mn);
        const float p    = __expf(sc - mn);
        m = mn;
        l = l * corr + p;
        acc.x = acc.x * corr + p * vv.x;
        acc.y = acc.y * corr + p * vv.y;
        acc.z = acc.z * corr + p * vv.z;
        acc.w = acc.w * corr + p * vv.w;
    }

    // ---- combine the NWARPS warps of this CTA ----
    __shared__ float sm_m[NWARPS];
    __shared__ float sm_l[NWARPS];
    __shared__ float sm_acc[NWARPS][DD];

    if (lane == 0) { sm_m[w] = m; sm_l[w] = l; }
    sm_acc[w][lane * 4 + 0] = acc.x;
    sm_acc[w][lane * 4 + 1] = acc.y;
    sm_acc[w][lane * 4 + 2] = acc.z;
    sm_acc[w][lane * 4 + 3] = acc.w;
    __syncthreads();

    if (w == 0) {
        float M = -CUDART_INF_F;
#pragma unroll
        for (int i = 0; i < NWARPS; i++) M = fmaxf(M, sm_m[i]);

        float  L = 0.f;
        float4 o = make_float4(0.f, 0.f, 0.f, 0.f);
#pragma unroll
        for (int i = 0; i < NWARPS; i++) {
            if (sm_l[i] == 0.f) continue;   // warp saw no positions
            const float c = __expf(sm_m[i] - M);
            L += c * sm_l[i];
            o.x += c * sm_acc[i][lane * 4 + 0];
            o.y += c * sm_acc[i][lane * 4 + 1];
            o.z += c * sm_acc[i][lane * 4 + 2];
            o.w += c * sm_acc[i][lane * 4 + 3];
        }
        g_pm[bid] = M;
        g_pl[bid] = L;
        reinterpret_cast<float4*>(g_pacc + (size_t)bid * DD)[lane] = o;

        // ---- fused cross-split combine: last CTA per (b,h) merges ----
        __threadfence();
        int done = 0;
        if (lane == 0) done = atomicAdd(&g_cnt[bh], 1);
        done = __shfl_sync(0xffffffffu, done, 0);

        if (done == NSPLITS - 1) {
            float GM = -CUDART_INF_F;
#pragma unroll
            for (int i = 0; i < NSPLITS; i++)
                GM = fmaxf(GM, __ldcg(&g_pm[bh * NSPLITS + i]));

            float  GL = 0.f;
            float4 go = make_float4(0.f, 0.f, 0.f, 0.f);
#pragma unroll 4
            for (int i = 0; i < NSPLITS; i++) {
                const int idx = bh * NSPLITS + i;
                const float li = __ldcg(&g_pl[idx]);
                if (li == 0.f) continue;
                const float c = __expf(__ldcg(&g_pm[idx]) - GM);
                GL += c * li;
                const float4 a = __ldcg(reinterpret_cast<const float4*>(
                    g_pacc + (size_t)idx * DD) + lane);
                go.x += c * a.x; go.y += c * a.y;
                go.z += c * a.z; go.w += c * a.w;
            }
            const float inv = 1.f / GL;
            const float4 r = make_float4(go.x * inv, go.y * inv,
                                         go.z * inv, go.w * inv);
            reinterpret_cast<float4*>(out + (size_t)bh * DD)[lane] = r;

            if (lane == 0) g_cnt[bh] = 0;   // reset for next graph replay
        }
    }
}

// ---------------------------------------------------------------------------
extern "C" void kernel_launch(void* const* d_in, const int* in_sizes, int n_in,
                              void* d_out, int out_size) {
    // Identify inputs defensively by element count:
    //   x: B*H*D = 16384 fp32, kv: 2*B*S*H*D fp32 (largest), current_pos: 1 int
    const float* x  = nullptr;
    const float* kv = nullptr;
    const int*   cp = nullptr;
    long long best_kv = -1;
    for (int i = 0; i < n_in; i++) {
        if (in_sizes[i] == 1) cp = (const int*)d_in[i];
        else if (in_sizes[i] == BB * HH * DD) x = (const float*)d_in[i];
        else if ((long long)in_sizes[i] > best_kv) {
            best_kv = in_sizes[i];
            kv = (const float*)d_in[i];
        }
    }

    attn_split_kernel<<<NBH * NSPLITS, NWARPS * 32>>>(x, kv, cp, (float*)d_out);
}

// round 16
// speedup vs baseline: 1.0119x; 1.0007x over previous
#include <cuda_runtime.h>
#include <math_constants.h>

// Problem shape (fixed by the dataset)
#define BB 4
#define HH 32
#define DD 128
#define SS 8192
#define NSPLITS 16        // measured-optimal granularity; grid = 2048 CTAs
#define NWARPS 2          // 64-thread CTAs -> ~28 warps/SM, single wave
#define NBH (BB * HH)     // 128
#define SCALE 0.08838834764831845f   // 1/sqrt(128)

// Scratch for split-KV partials (device globals: allocation-free)
__device__ float g_pm[NBH * NSPLITS];
__device__ float g_pl[NBH * NSPLITS];
__device__ float g_pacc[NBH * NSPLITS * DD];
__device__ int   g_cnt[NBH];   // zero-init; self-resetting -> graph-replay safe

__device__ __forceinline__ float warp_sum(float v) {
#pragma unroll
    for (int o = 16; o > 0; o >>= 1)
        v += __shfl_xor_sync(0xffffffffu, v, o);
    return v;
}

__device__ __forceinline__ float dot4(const float4 a, const float4 b) {
    return a.x * b.x + a.y * b.y + a.z * b.z + a.w * b.w;
}

__device__ __forceinline__ float4 ldcs4(const float* p) {
    return __ldcs(reinterpret_cast<const float4*>(p));
}

// ---------------------------------------------------------------------------
// FINAL champion (best measured 82.4us; kernel is exactly at the achieved HBM
// streaming bandwidth: dur x 6.26TB/s == 537MB compulsory KV traffic).
// One CTA = one (b, h, split). Warps stride positions inside the split chunk.
// Lane owns dims [4*lane, 4*lane+4). 4x position unroll -> 8 streaming float4
// loads in flight per warp (interior optimum: MLP 4->86.1, 8->82.4, 16->96.3).
// Fused combine: last CTA per (b,h) merges split partials via atomic counter.
// Falsified alternatives: higher occupancy (R3), larger DRAM granule (R4/R8),
// single-warp CTAs (R9), work-stealing (R10), deeper unroll (R12),
// software-pipelined load issue (R14). The ~79% DRAM-active plateau is the
// chip's achieved bulk-read ceiling, reproduced across all 12 variants.
// ---------------------------------------------------------------------------
__global__ __launch_bounds__(NWARPS * 32)
void attn_split_kernel(const float* __restrict__ x,
                       const float* __restrict__ kv,
                       const int*   __restrict__ cur_pos,
                       float*       __restrict__ out) {
    const int bid   = blockIdx.x;            // bh*NSPLITS + split
    const int bh    = bid / NSPLITS;
    const int h     = bh % HH;
    const int b     = bh / HH;
    const int split = bid % NSPLITS;

    const int tid  = threadIdx.x;
    const int lane = tid & 31;
    const int w    = tid >> 5;

    const int len   = *cur_pos + 1;                      // valid positions
    const int chunk = (len + NSPLITS - 1) / NSPLITS;
    const int s0    = split * chunk;
    const int s1    = min(len, s0 + chunk);

    // q[b,0,h,:] — lane's 4 dims
    const float4 q = *reinterpret_cast<const float4*>(
        x + (size_t)(b * HH + h) * DD + lane * 4);

    const size_t row_stride = (size_t)HH * DD;           // stride over s
    const size_t kv_half    = (size_t)BB * SS * HH * DD; // K->V offset
    const float* Kp = kv + (size_t)b * SS * row_stride + (size_t)h * DD + lane * 4;
    const float* Vp = Kp + kv_half;

    float  m = -CUDART_INF_F;
    float  l = 0.f;
    float4 acc = make_float4(0.f, 0.f, 0.f, 0.f);

    int s = s0 + w;
    // 4x unroll: 8 streaming float4 loads in flight before dependent math,
    // single max/rescale per group -> 4 independent __expf's.
    for (; s + 3 * NWARPS < s1; s += 4 * NWARPS) {
        const float4 k0 = ldcs4(Kp + (size_t)(s             ) * row_stride);
        const float4 v0 = ldcs4(Vp + (size_t)(s             ) * row_stride);
        const float4 k1 = ldcs4(Kp + (size_t)(s +     NWARPS) * row_stride);
        const float4 v1 = ldcs4(Vp + (size_t)(s +     NWARPS) * row_stride);
        const float4 k2 = ldcs4(Kp + (size_t)(s + 2 * NWARPS) * row_stride);
        const float4 v2 = ldcs4(Vp + (size_t)(s + 2 * NWARPS) * row_stride);
        const float4 k3 = ldcs4(Kp + (size_t)(s + 3 * NWARPS) * row_stride);
        const float4 v3 = ldcs4(Vp + (size_t)(s + 3 * NWARPS) * row_stride);

        const float sc0 = warp_sum(dot4(k0, q)) * SCALE;
        const float sc1 = warp_sum(dot4(k1, q)) * SCALE;
        const float sc2 = warp_sum(dot4(k2, q)) * SCALE;
        const float sc3 = warp_sum(dot4(k3, q)) * SCALE;

        const float mn = fmaxf(fmaxf(fmaxf(m, sc0), fmaxf(sc1, sc2)), sc3);
        const float corr = __expf(m - mn);
        const float p0 = __expf(sc0 - mn);
        const float p1 = __expf(sc1 - mn);
        const float p2 = __expf(sc2 - mn);
        const float p3 = __expf(sc3 - mn);
        m = mn;
        l = l * corr + ((p0 + p1) + (p2 + p3));
        acc.x = acc.x * corr + (p0 * v0.x + p1 * v1.x) + (p2 * v2.x + p3 * v3.x);
        acc.y = acc.y * corr + (p0 * v0.y + p1 * v1.y) + (p2 * v2.y + p3 * v3.y);
        acc.z = acc.z * corr + (p0 * v0.z + p1 * v1.z) + (p2 * v2.z + p3 * v3.z);
        acc.w = acc.w * corr + (p0 * v0.w + p1 * v1.w) + (p2 * v2.w + p3 * v3.w);
    }
    for (; s < s1; s += NWARPS) {
        const float4 kk = ldcs4(Kp + (size_t)s * row_stride);
        const float4 vv = ldcs4(Vp + (size_t)s * row_stride);
        const float sc = warp_sum(dot4(kk, q)) * SCALE;
        const float mn   = fmaxf(m, sc);
        const float corr = __expf(m - mn);
        const float p    = __expf(sc - mn);
        m = mn;
        l = l * corr + p;
        acc.x = acc.x * corr + p * vv.x;
        acc.y = acc.y * corr + p * vv.y;
        acc.z = acc.z * corr + p * vv.z;
        acc.w = acc.w * corr + p * vv.w;
    }

    // ---- combine the NWARPS warps of this CTA ----
    __shared__ float sm_m[NWARPS];
    __shared__ float sm_l[NWARPS];
    __shared__ float sm_acc[NWARPS][DD];

    if (lane == 0) { sm_m[w] = m; sm_l[w] = l; }
    sm_acc[w][lane * 4 + 0] = acc.x;
    sm_acc[w][lane * 4 + 1] = acc.y;
    sm_acc[w][lane * 4 + 2] = acc.z;
    sm_acc[w][lane * 4 + 3] = acc.w;
    __syncthreads();

    if (w == 0) {
        float M = -CUDART_INF_F;
#pragma unroll
        for (int i = 0; i < NWARPS; i++) M = fmaxf(M, sm_m[i]);

        float  L = 0.f;
        float4 o = make_float4(0.f, 0.f, 0.f, 0.f);
#pragma unroll
        for (int i = 0; i < NWARPS; i++) {
            if (sm_l[i] == 0.f) continue;   // warp saw no positions
            const float c = __expf(sm_m[i] - M);
            L += c * sm_l[i];
            o.x += c * sm_acc[i][lane * 4 + 0];
            o.y += c * sm_acc[i][lane * 4 + 1];
            o.z += c * sm_acc[i][lane * 4 + 2];
            o.w += c * sm_acc[i][lane * 4 + 3];
        }
        g_pm[bid] = M;
        g_pl[bid] = L;
        reinterpret_cast<float4*>(g_pacc + (size_t)bid * DD)[lane] = o;

        // ---- fused cross-split combine: last CTA per (b,h) merges ----
        __threadfence();
        int done = 0;
        if (lane == 0) done = atomicAdd(&g_cnt[bh], 1);
        done = __shfl_sync(0xffffffffu, done, 0);

        if (done == NSPLITS - 1) {
            float GM = -CUDART_INF_F;
#pragma unroll
            for (int i = 0; i < NSPLITS; i++)
                GM = fmaxf(GM, __ldcg(&g_pm[bh * NSPLITS + i]));

            float  GL = 0.f;
            float4 go = make_float4(0.f, 0.f, 0.f, 0.f);
#pragma unroll 4
            for (int i = 0; i < NSPLITS; i++) {
                const int idx = bh * NSPLITS + i;
                const float li = __ldcg(&g_pl[idx]);
                if (li == 0.f) continue;
                const float c = __expf(__ldcg(&g_pm[idx]) - GM);
                GL += c * li;
                const float4 a = __ldcg(reinterpret_cast<const float4*>(
                    g_pacc + (size_t)idx * DD) + lane);
                go.x += c * a.x; go.y += c * a.y;
                go.z += c * a.z; go.w += c * a.w;
            }
            const float inv = 1.f / GL;
            const float4 r = make_float4(go.x * inv, go.y * inv,
                                         go.z * inv, go.w * inv);
            reinterpret_cast<float4*>(out + (size_t)bh * DD)[lane] = r;

            if (lane == 0) g_cnt[bh] = 0;   // reset for next graph replay
        }
    }
}

// ---------------------------------------------------------------------------
extern "C" void kernel_launch(void* const* d_in, const int* in_sizes, int n_in,
                              void* d_out, int out_size) {
    // Identify inputs defensively by element count:
    //   x: B*H*D = 16384 fp32, kv: 2*B*S*H*D fp32 (largest), current_pos: 1 int
    const float* x  = nullptr;
    const float* kv = nullptr;
    const int*   cp = nullptr;
    long long best_kv = -1;
    for (int i = 0; i < n_in; i++) {
        if (in_sizes[i] == 1) cp = (const int*)d_in[i];
        else if (in_sizes[i] == BB * HH * DD) x = (const float*)d_in[i];
        else if ((long long)in_sizes[i] > best_kv) {
            best_kv = in_sizes[i];
            kv = (const float*)d_in[i];
        }
    }

    attn_split_kernel<<<NBH * NSPLITS, NWARPS * 32>>>(x, kv, cp, (float*)d_out);
}

// round 17
// speedup vs baseline: 1.0280x; 1.0159x over previous
#include <cuda_runtime.h>
#include <math_constants.h>

// Problem shape (fixed by the dataset)
#define BB 4
#define HH 32
#define DD 128
#define SS 8192
#define NSPLITS 16        // split groups per (b,h); grid = 2048 CTAs
#define NWARPS 2          // 64-thread CTAs -> ~28 warps/SM, single wave
#define NBH (BB * HH)     // 128
#define WSTRIDE (NSPLITS * NWARPS)   // 32: global warp stride over positions
#define SCALE 0.08838834764831845f   // 1/sqrt(128)

// Scratch for split-KV partials (device globals: allocation-free)
__device__ float g_pm[NBH * NSPLITS];
__device__ float g_pl[NBH * NSPLITS];
__device__ float g_pacc[NBH * NSPLITS * DD];
__device__ int   g_cnt[NBH];   // zero-init; self-resetting -> graph-replay safe

__device__ __forceinline__ float warp_sum(float v) {
#pragma unroll
    for (int o = 16; o > 0; o >>= 1)
        v += __shfl_xor_sync(0xffffffffu, v, o);
    return v;
}

__device__ __forceinline__ float dot4(const float4 a, const float4 b) {
    return a.x * b.x + a.y * b.y + a.z * b.z + a.w * b.w;
}

__device__ __forceinline__ float4 ldcs4(const float* p) {
    return __ldcs(reinterpret_cast<const float4*>(p));
}

// ---------------------------------------------------------------------------
// Champion shape (NSPLITS=16, 2-warp CTAs, MLP 8, fused combine) with ONE
// change: INTERLEAVED position assignment. Warp (split, w) owns positions
// p = split*NWARPS + w + 32*i. Since all CTAs progress at similar rates, the
// 32 warps of each (b,h) group sweep a single moving band of consecutive
// positions, and all 32 head-groups read the SAME position rows concurrently
// -> dense instantaneous DRAM footprint (row-buffer locality in time).
// Per-warp: identical granule (512B), identical MLP (8 loads in flight).
// ---------------------------------------------------------------------------
__global__ __launch_bounds__(NWARPS * 32)
void attn_split_kernel(const float* __restrict__ x,
                       const float* __restrict__ kv,
                       const int*   __restrict__ cur_pos,
                       float*       __restrict__ out) {
    const int bid   = blockIdx.x;            // bh*NSPLITS + split
    const int bh    = bid / NSPLITS;
    const int h     = bh % HH;
    const int b     = bh / HH;
    const int split = bid % NSPLITS;

    const int tid  = threadIdx.x;
    const int lane = tid & 31;
    const int w    = tid >> 5;

    const int len = *cur_pos + 1;                        // valid positions

    // q[b,0,h,:] — lane's 4 dims
    const float4 q = *reinterpret_cast<const float4*>(
        x + (size_t)(b * HH + h) * DD + lane * 4);

    const size_t row_stride = (size_t)HH * DD;           // stride over s
    const size_t kv_half    = (size_t)BB * SS * HH * DD; // K->V offset
    const float* Kp = kv + (size_t)b * SS * row_stride + (size_t)h * DD + lane * 4;
    const float* Vp = Kp + kv_half;

    float  m = -CUDART_INF_F;
    float  l = 0.f;
    float4 acc = make_float4(0.f, 0.f, 0.f, 0.f);

    // interleaved start: this warp's first position
    int s = split * NWARPS + w;
    // 4x unroll: 8 streaming float4 loads in flight before dependent math,
    // single max/rescale per group -> 4 independent __expf's.
    for (; s + 3 * WSTRIDE < len; s += 4 * WSTRIDE) {
        const float4 k0 = ldcs4(Kp + (size_t)(s              ) * row_stride);
        const float4 v0 = ldcs4(Vp + (size_t)(s              ) * row_stride);
        const float4 k1 = ldcs4(Kp + (size_t)(s +     WSTRIDE) * row_stride);
        const float4 v1 = ldcs4(Vp + (size_t)(s +     WSTRIDE) * row_stride);
        const float4 k2 = ldcs4(Kp + (size_t)(s + 2 * WSTRIDE) * row_stride);
        const float4 v2 = ldcs4(Vp + (size_t)(s + 2 * WSTRIDE) * row_stride);
        const float4 k3 = ldcs4(Kp + (size_t)(s + 3 * WSTRIDE) * row_stride);
        const float4 v3 = ldcs4(Vp + (size_t)(s + 3 * WSTRIDE) * row_stride);

        const float sc0 = warp_sum(dot4(k0, q)) * SCALE;
        const float sc1 = warp_sum(dot4(k1, q)) * SCALE;
        const float sc2 = warp_sum(dot4(k2, q)) * SCALE;
        const float sc3 = warp_sum(dot4(k3, q)) * SCALE;

        const float mn = fmaxf(fmaxf(fmaxf(m, sc0), fmaxf(sc1, sc2)), sc3);
        const float corr = __expf(m - mn);
        const float p0 = __expf(sc0 - mn);
        const float p1 = __expf(sc1 - mn);
        const float p2 = __expf(sc2 - mn);
        const float p3 = __expf(sc3 - mn);
        m = mn;
        l = l * corr + ((p0 + p1) + (p2 + p3));
        acc.x = acc.x * corr + (p0 * v0.x + p1 * v1.x) + (p2 * v2.x + p3 * v3.x);
        acc.y = acc.y * corr + (p0 * v0.y + p1 * v1.y) + (p2 * v2.y + p3 * v3.y);
        acc.z = acc.z * corr + (p0 * v0.z + p1 * v1.z) + (p2 * v2.z + p3 * v3.z);
        acc.w = acc.w * corr + (p0 * v0.w + p1 * v1.w) + (p2 * v2.w + p3 * v3.w);
    }
    for (; s < len; s += WSTRIDE) {
        const float4 kk = ldcs4(Kp + (size_t)s * row_stride);
        const float4 vv = ldcs4(Vp + (size_t)s * row_stride);
        const float sc = warp_sum(dot4(kk, q)) * SCALE;
        const float mn   = fmaxf(m, sc);
        const float corr = __expf(m - mn);
        const float p    = __expf(sc - mn);
        m = mn;
        l = l * corr + p;
        acc.x = acc.x * corr + p * vv.x;
        acc.y = acc.y * corr + p * vv.y;
        acc.z = acc.z * corr + p * vv.z;
        acc.w = acc.w * corr + p * vv.w;
    }

    // ---- combine the NWARPS warps of this CTA ----
    __shared__ float sm_m[NWARPS];
    __shared__ float sm_l[NWARPS];
    __shared__ float sm_acc[NWARPS][DD];

    if (lane == 0) { sm_m[w] = m; sm_l[w] = l; }
    sm_acc[w][lane * 4 + 0] = acc.x;
    sm_acc[w][lane * 4 + 1] = acc.y;
    sm_acc[w][lane * 4 + 2] = acc.z;
    sm_acc[w][lane * 4 + 3] = acc.w;
    __syncthreads();

    if (w == 0) {
        float M = -CUDART_INF_F;
#pragma unroll
        for (int i = 0; i < NWARPS; i++) M = fmaxf(M, sm_m[i]);

        float  L = 0.f;
        float4 o = make_float4(0.f, 0.f, 0.f, 0.f);
#pragma unroll
        for (int i = 0; i < NWARPS; i++) {
            if (sm_l[i] == 0.f) continue;   // warp saw no positions
            const float c = __expf(sm_m[i] - M);
            L += c * sm_l[i];
            o.x += c * sm_acc[i][lane * 4 + 0];
            o.y += c * sm_acc[i][lane * 4 + 1];
            o.z += c * sm_acc[i][lane * 4 + 2];
            o.w += c * sm_acc[i][lane * 4 + 3];
        }
        g_pm[bid] = M;
        g_pl[bid] = L;
        reinterpret_cast<float4*>(g_pacc + (size_t)bid * DD)[lane] = o;

        // ---- fused cross-split combine: last CTA per (b,h) merges ----
        __threadfence();
        int done = 0;
        if (lane == 0) done = atomicAdd(&g_cnt[bh], 1);
        done = __shfl_sync(0xffffffffu, done, 0);

        if (done == NSPLITS - 1) {
            float GM = -CUDART_INF_F;
#pragma unroll
            for (int i = 0; i < NSPLITS; i++)
                GM = fmaxf(GM, __ldcg(&g_pm[bh * NSPLITS + i]));

            float  GL = 0.f;
            float4 go = make_float4(0.f, 0.f, 0.f, 0.f);
#pragma unroll 4
            for (int i = 0; i < NSPLITS; i++) {
                const int idx = bh * NSPLITS + i;
                const float li = __ldcg(&g_pl[idx]);
                if (li == 0.f) continue;
                const float c = __expf(__ldcg(&g_pm[idx]) - GM);
                GL += c * li;
                const float4 a = __ldcg(reinterpret_cast<const float4*>(
                    g_pacc + (size_t)idx * DD) + lane);
                go.x += c * a.x; go.y += c * a.y;
                go.z += c * a.z; go.w += c * a.w;
            }
            const float inv = 1.f / GL;
            const float4 r = make_float4(go.x * inv, go.y * inv,
                                         go.z * inv, go.w * inv);
            reinterpret_cast<float4*>(out + (size_t)bh * DD)[lane] = r;

            if (lane == 0) g_cnt[bh] = 0;   // reset for next graph replay
        }
    }
}

// ---------------------------------------------------------------------------
extern "C" void kernel_launch(void* const* d_in, const int* in_sizes, int n_in,
                              void* d_out, int out_size) {
    // Identify inputs defensively by element count:
    //   x: B*H*D = 16384 fp32, kv: 2*B*S*H*D fp32 (largest), current_pos: 1 int
    const float* x  = nullptr;
    const float* kv = nullptr;
    const int*   cp = nullptr;
    long long best_kv = -1;
    for (int i = 0; i < n_in; i++) {
        if (in_sizes[i] == 1) cp = (const int*)d_in[i];
        else if (in_sizes[i] == BB * HH * DD) x = (const float*)d_in[i];
        else if ((long long)in_sizes[i] > best_kv) {
            best_kv = in_sizes[i];
            kv = (const float*)d_in[i];
        }
    }

    attn_split_kernel<<<NBH * NSPLITS, NWARPS * 32>>>(x, kv, cp, (float*)d_out);
}